// round 1
// baseline (speedup 1.0000x reference)
#include <cuda_runtime.h>

// CLSTM: x (4,1,64,256,256) f32, Wx (4,1,5,5), Wh (4,1,5,5), b (4), direction=0.
// Scan over D=64. Per step:
//   z = relu(conv5x5(x_t, Wx)) + relu(conv5x5(h_prev, Wh)) + b   (channels 0,2,3 only)
//   i = sigmoid(z0); cg = tanh(z2); o = sigmoid(z3)
//   c = (cg + c_prev) * i;  h = o * tanh(c)
// Output layout identical to x: out[b][t][y][x].

#define HH 256
#define WW 256
#define BB 4
#define TT 64

// cell-state scratch (4 MB). Never needs init: t=0 kernel writes it (FIRST path).
__device__ float g_c[BB * HH * WW];

__device__ __forceinline__ float fast_tanh(float v) {
    float y;
    asm("tanh.approx.f32 %0, %1;" : "=f"(y) : "f"(v));
    return y;
}
__device__ __forceinline__ float fast_sigmoid(float v) {
    return 0.5f * fast_tanh(0.5f * v) + 0.5f;
}

// Tile: 32 wide (lanes) x 32 tall (8 ty * 4 rows/thread). Halo 2 each side -> 36x36 smem.
template <bool FIRST>
__global__ __launch_bounds__(256)
void clstm_step(const float* __restrict__ x,
                const float* __restrict__ Wx,
                const float* __restrict__ Wh,
                const float* __restrict__ bias,
                float* __restrict__ out,
                int t)
{
    __shared__ float xs[36 * 36];
    __shared__ float hs[36 * 36];
    __shared__ float wsm[204];   // [0..99]=Wx, [100..199]=Wh, [200..203]=b

    const int lane = threadIdx.x;          // 0..31
    const int ty   = threadIdx.y;          // 0..7
    const int tid  = ty * 32 + lane;       // 0..255
    const int b    = blockIdx.z;
    const int x0   = blockIdx.x * 32;
    const int y0   = blockIdx.y * 32;

    if (tid < 204) {
        float v;
        if (tid < 100)      v = Wx[tid];
        else if (tid < 200) v = Wh[tid - 100];
        else                v = bias[tid - 200];
        wsm[tid] = v;
    }

    const float* xsrc = x   + (size_t)(b * TT + t)       * (HH * WW);
    const float* hsrc = out + (size_t)(b * TT + (t - 1)) * (HH * WW);

    #pragma unroll
    for (int pass = 0; pass < 6; pass++) {
        int idx = tid + pass * 256;
        if (idx < 36 * 36) {
            int rr = idx / 36, cc = idx % 36;
            int gy = y0 + rr - 2, gx = x0 + cc - 2;
            bool ok = (gy >= 0) && (gy < HH) && (gx >= 0) && (gx < WW);
            xs[idx] = ok ? xsrc[gy * WW + gx] : 0.0f;
            if (!FIRST) hs[idx] = ok ? hsrc[gy * WW + gx] : 0.0f;
        }
    }
    __syncthreads();

    // Accumulators: separate x-conv and h-conv (relu applied to each before summing).
    float ax0[4] = {0.f, 0.f, 0.f, 0.f};
    float ax2[4] = {0.f, 0.f, 0.f, 0.f};
    float ax3[4] = {0.f, 0.f, 0.f, 0.f};
    float ah0[4] = {0.f, 0.f, 0.f, 0.f};
    float ah2[4] = {0.f, 0.f, 0.f, 0.f};
    float ah3[4] = {0.f, 0.f, 0.f, 0.f};

    const int rbase = ty * 4;

    #pragma unroll
    for (int ky = 0; ky < 5; ky++) {
        #pragma unroll
        for (int kx = 0; kx < 5; kx++) {
            const int tap = ky * 5 + kx;
            const float w0 = wsm[0 * 25 + tap];
            const float w2 = wsm[2 * 25 + tap];
            const float w3 = wsm[3 * 25 + tap];
            float v0 = 0.f, v2 = 0.f, v3 = 0.f;
            if (!FIRST) {
                v0 = wsm[100 + 0 * 25 + tap];
                v2 = wsm[100 + 2 * 25 + tap];
                v3 = wsm[100 + 3 * 25 + tap];
            }
            #pragma unroll
            for (int r = 0; r < 4; r++) {
                const int soff = (rbase + r + ky) * 36 + lane + kx;
                float xv = xs[soff];
                ax0[r] += w0 * xv;
                ax2[r] += w2 * xv;
                ax3[r] += w3 * xv;
                if (!FIRST) {
                    float hv = hs[soff];
                    ah0[r] += v0 * hv;
                    ah2[r] += v2 * hv;
                    ah3[r] += v3 * hv;
                }
            }
        }
    }

    const float b0 = wsm[200];
    const float b2 = wsm[202];
    const float b3 = wsm[203];

    float* cptr = g_c + b * (HH * WW);
    float* optr = out + (size_t)(b * TT + t) * (HH * WW);
    const int gx = x0 + lane;

    #pragma unroll
    for (int r = 0; r < 4; r++) {
        const int gy  = y0 + rbase + r;
        const int pix = gy * WW + gx;

        float z0 = fmaxf(ax0[r], 0.f) + b0;
        float z2 = fmaxf(ax2[r], 0.f) + b2;
        float z3 = fmaxf(ax3[r], 0.f) + b3;
        if (!FIRST) {
            z0 += fmaxf(ah0[r], 0.f);
            z2 += fmaxf(ah2[r], 0.f);
            z3 += fmaxf(ah3[r], 0.f);
        }

        float ig = fast_sigmoid(z0);
        float cg = fast_tanh(z2);
        float og = fast_sigmoid(z3);

        float cprev = FIRST ? 0.f : cptr[pix];
        float cn = (cg + cprev) * ig;
        cptr[pix] = cn;
        optr[pix] = og * fast_tanh(cn);
    }
}

extern "C" void kernel_launch(void* const* d_in, const int* in_sizes, int n_in,
                              void* d_out, int out_size)
{
    const float* x    = (const float*)d_in[0];
    const float* Wx   = (const float*)d_in[1];
    const float* Wh   = (const float*)d_in[2];
    const float* bias = (const float*)d_in[3];
    float* out        = (float*)d_out;

    dim3 block(32, 8);
    dim3 grid(WW / 32, HH / 32, BB);   // 8 x 8 x 4 = 256 blocks per step

    clstm_step<true><<<grid, block>>>(x, Wx, Wh, bias, out, 0);
    for (int t = 1; t < TT; t++) {
        clstm_step<false><<<grid, block>>>(x, Wx, Wh, bias, out, t);
    }
}